// round 12
// baseline (speedup 1.0000x reference)
#include <cuda_runtime.h>
#include <cuda_bf16.h>
#include <cstdint>

#define TT  15
#define C1I 6
#define HI  224
#define WI  224
#define C1O 30
#define HP  114
#define WP  114
#define C2O 240
#define HO  112
#define WO  112

#define WSCALE   112.0f
#define INV_WS   (1.0f / 112.0f)
#define THR_C    1120            // 10 * WSCALE

// Input, channel-last bf16: [t][y][x][8]
__device__ __align__(16) unsigned short g_inb[(size_t)TT * HI * WI * 8];
// Layer-1 pooled spikes, channel-last s8 (0/1), padded: [t][y114][x114][32]
__device__ __align__(16) signed char g_spk1s8[(size_t)TT * HP * WP * 32];
// Conv1 B-fragments (bf16), nt-paired: [s13][jp2][lane32] uint4
__device__ __align__(16) uint4 g_Bf1p[13 * 2 * 32];
// Conv2 B-fragments (s8, m16n8k32), nt-paired: [s9][nh2][jp8][lane32] uint4
__device__ __align__(16) uint4 g_Bf2s[9 * 2 * 8 * 32];

__device__ __forceinline__ uint32_t cvta_smem(const void* p) {
    uint32_t a;
    asm("{ .reg .u64 t; cvta.to.shared.u64 t, %1; cvt.u32.u64 %0, t; }"
        : "=r"(a) : "l"(p));
    return a;
}
__device__ __forceinline__ unsigned short f2bf(float f) {
    __nv_bfloat16 b = __float2bfloat16(f);
    return *(unsigned short*)&b;
}

#define CP16(dst, src) \
    asm volatile("cp.async.cg.shared.global [%0], [%1], 16;" \
                 :: "r"(dst), "l"(src) : "memory")
#define CP16Z(dst, src, sz) \
    asm volatile("cp.async.cg.shared.global [%0], [%1], 16, %2;" \
                 :: "r"(dst), "l"(src), "r"(sz) : "memory")
#define CP_COMMIT() asm volatile("cp.async.commit_group;" ::: "memory")
#define CP_WAIT(n)  asm volatile("cp.async.wait_group %0;" :: "n"(n) : "memory")

// ---------------------------------------------------------------------------
// Prep: conv1 bf16 frags (nt-paired) + conv2 s8 frags (m16n8k32, nt-paired).
// ---------------------------------------------------------------------------
__global__ __launch_bounds__(256) void k_prep(const float* __restrict__ w1,
                                              const float* __restrict__ w2) {
    int i = blockIdx.x * 256 + threadIdx.x;
    if (i < 13 * 2 * 32) {                       // conv1: k = tap*8+ic, bf16
        int l = i & 31, jp = (i >> 5) & 1, s = i >> 6;
        uint32_t q[4];
#pragma unroll
        for (int h = 0; h < 2; h++) {
            int nt = 2 * jp + h;
            int oc = nt * 8 + (l >> 2);
#pragma unroll
            for (int r = 0; r < 2; r++) {
                uint32_t pk = 0;
#pragma unroll
                for (int e = 0; e < 2; e++) {
                    int k = s * 16 + (l & 3) * 2 + r * 8 + e;
                    int tap = k >> 3, ic = k & 7;
                    float w = (ic < 6 && tap < 25 && oc < 30)
                            ? w1[(oc * 6 + ic) * 25 + tap] : 0.0f;
                    pk |= (uint32_t)f2bf(w) << (16 * e);
                }
                q[h * 2 + r] = pk;
            }
        }
        g_Bf1p[i] = make_uint4(q[0], q[1], q[2], q[3]);
    } else if (i < 13 * 2 * 32 + 9 * 2 * 8 * 32) {    // conv2 s8: k = tap*32+ic
        int j = i - 13 * 2 * 32;
        int l = j & 31, jp = (j >> 5) & 7, nh = (j >> 8) & 1, s = j >> 9;
        uint32_t q[4] = {0, 0, 0, 0};
#pragma unroll
        for (int h = 0; h < 2; h++) {
            int nt = 2 * jp + h;
            if (nt < 15) {
                int oc = nh * 120 + nt * 8 + (l >> 2);
#pragma unroll
                for (int r = 0; r < 2; r++) {
                    uint32_t pk = 0;
#pragma unroll
                    for (int e = 0; e < 4; e++) {
                        int ic = 4 * (l & 3) + r * 16 + e;    // k within tap
                        int qv = 0;
                        if (ic < 30) {
                            float w = w2[(oc * 30 + ic) * 9 + s];
                            qv = __float2int_rn(w * WSCALE);
                            qv = max(-127, min(127, qv));
                        }
                        pk |= ((uint32_t)(qv & 0xFF)) << (8 * e);
                    }
                    q[h * 2 + r] = pk;
                }
            }
        }
        g_Bf2s[j] = make_uint4(q[0], q[1], q[2], q[3]);
    }
}

// ---------------------------------------------------------------------------
// Convert input NCHW f32 -> channel-last bf16.
// ---------------------------------------------------------------------------
__global__ __launch_bounds__(256) void k_cvt(const float* __restrict__ in) {
    int p = blockIdx.x * 256 + threadIdx.x;
    if (p >= TT * HI * WI) return;
    int t  = p / (HI * WI);
    int px = p % (HI * WI);
    const float* b = in + (size_t)t * C1I * HI * WI + px;
    unsigned short r[8];
#pragma unroll
    for (int ic = 0; ic < 6; ic++) r[ic] = f2bf(b[(size_t)ic * HI * WI]);
    r[6] = 0; r[7] = 0;
    *(uint4*)(g_inb + (size_t)p * 8) = *(uint4*)r;
}

// ---------------------------------------------------------------------------
// Kernel 1: conv1 via bf16 mma.sync + fire(15) + maxpool -> s8 spike map.
// CTA (256 thr, 8 warps): 16x16 conv-px tile (M=256), N=32, K=208.
// ---------------------------------------------------------------------------
#define C1_IMG   0
#define C1_C     6400
#define C1_SMEM  (6400 + 32768)

__global__ __launch_bounds__(256) void k_conv1() {
    extern __shared__ __align__(16) unsigned char sm[];
    const uint32_t smb = cvta_smem(sm);
    float* sC = (float*)(sm + C1_C);           // [py16][px16][oc32]

    const int t   = blockIdx.z;
    const int X0  = blockIdx.x * 16;
    const int Y0  = blockIdx.y * 16;
    const int tid = threadIdx.x;
    const int wid = tid >> 5;
    const int l   = tid & 31;

    const unsigned short* inb = g_inb + (size_t)t * HI * WI * 8;
    for (int i = tid; i < 400; i += 256) {
        int ly = i / 20, lx = i % 20;
        int gy = Y0 - 2 + ly, gx = X0 - 2 + lx;
        bool ok = (unsigned)gy < (unsigned)HI && (unsigned)gx < (unsigned)WI;
        int cy = ok ? gy : 0, cx = ok ? gx : 0;
        const unsigned short* src = inb + ((size_t)cy * WI + cx) * 8;
        CP16Z(smb + C1_IMG + i * 16, src, ok ? 16 : 0);
    }
    CP_COMMIT();
    CP_WAIT(0);
    __syncthreads();

    float c[2][4][4];
#pragma unroll
    for (int i = 0; i < 2; i++)
#pragma unroll
        for (int nt = 0; nt < 4; nt++)
#pragma unroll
            for (int j = 0; j < 4; j++) c[i][nt][j] = 0.0f;

    const int pxl  = l & 15;
    const int tsel = l >> 4;

    for (int s = 0; s < 13; s++) {
        int tp = 2 * s + tsel; if (tp > 24) tp = 24;
        int kh = tp / 5, kw = tp - 5 * kh;
#pragma unroll
        for (int i = 0; i < 2; i++) {
            int py = 2 * wid + i;
            uint32_t addr = smb + C1_IMG + ((py + kh) * 20 + pxl + kw) * 16;
            uint32_t a0, a1, a2, a3;
            asm volatile("ldmatrix.sync.aligned.m8n8.x4.shared.b16 {%0,%1,%2,%3}, [%4];"
                         : "=r"(a0), "=r"(a1), "=r"(a2), "=r"(a3) : "r"(addr));
            const uint4* bp = g_Bf1p + s * 64 + l;
#pragma unroll
            for (int jp = 0; jp < 2; jp++) {
                uint4 b = __ldg(bp + jp * 32);
                asm volatile(
                    "mma.sync.aligned.m16n8k16.row.col.f32.bf16.bf16.f32 "
                    "{%0,%1,%2,%3}, {%4,%5,%6,%7}, {%8,%9}, {%0,%1,%2,%3};"
                    : "+f"(c[i][2*jp][0]), "+f"(c[i][2*jp][1]),
                      "+f"(c[i][2*jp][2]), "+f"(c[i][2*jp][3])
                    : "r"(a0), "r"(a1), "r"(a2), "r"(a3), "r"(b.x), "r"(b.y));
                asm volatile(
                    "mma.sync.aligned.m16n8k16.row.col.f32.bf16.bf16.f32 "
                    "{%0,%1,%2,%3}, {%4,%5,%6,%7}, {%8,%9}, {%0,%1,%2,%3};"
                    : "+f"(c[i][2*jp+1][0]), "+f"(c[i][2*jp+1][1]),
                      "+f"(c[i][2*jp+1][2]), "+f"(c[i][2*jp+1][3])
                    : "r"(a0), "r"(a1), "r"(a2), "r"(a3), "r"(b.z), "r"(b.w));
            }
        }
    }

#pragma unroll
    for (int i = 0; i < 2; i++) {
        int py = 2 * wid + i;
        int px0 = l >> 2, oc0 = 2 * (l & 3);
#pragma unroll
        for (int nt = 0; nt < 4; nt++) {
            *(float2*)(sC + (py * 16 + px0) * 32 + nt * 8 + oc0)
                = make_float2(c[i][nt][0], c[i][nt][1]);
            *(float2*)(sC + (py * 16 + px0 + 8) * 32 + nt * 8 + oc0)
                = make_float2(c[i][nt][2], c[i][nt][3]);
        }
    }
    __syncthreads();

    {   // pool 2x2 + fire(15) -> 8 s8 bytes per thread
        int ocq = tid & 3;
        int ppx = (tid >> 2) & 7;
        int ppy = tid >> 5;
        uint32_t w01[2];
#pragma unroll
        for (int w = 0; w < 2; w++) {
            uint32_t word = 0;
#pragma unroll
            for (int j = 0; j < 4; j++) {
                int oc = ocq * 8 + w * 4 + j;
                const float* p = sC + ((2 * ppy) * 16 + 2 * ppx) * 32 + oc;
                float m = fmaxf(fmaxf(p[0], p[32]), fmaxf(p[16 * 32], p[17 * 32]));
                if (m > 15.0f) word |= 1u << (8 * j);
            }
            w01[w] = word;
        }
        int y = blockIdx.y * 8 + ppy + 1;
        int x = blockIdx.x * 8 + ppx + 1;
        *(uint2*)(g_spk1s8 + ((size_t)(t * HP + y) * WP + x) * 32 + ocq * 8)
            = make_uint2(w01[0], w01[1]);
    }
}

// ---------------------------------------------------------------------------
// Kernel 2: conv2 via s8 mma.m16n8k32 + fire(10).
// CTA (256 thr, 8 warps = 4 mt x 2 nh): 16x4 px tile (M=64), N=240, K=9x32.
// A: halo [6][18][32] s8, unit-swizzled; k32 step s = tap s (kh,kw shift).
// B: 3-stage cp.async pipeline of s8 fragments.
// ---------------------------------------------------------------------------
#define HB_Y    6
#define HB_X    18
#define SB_OFF  3456                   // 6*18*32
#define SB_STG  8192
#define SM2_TOT (SB_OFF + 3 * SB_STG)

__global__ __launch_bounds__(256, 2) void k_conv2(float* __restrict__ spk,
                                                  float* __restrict__ pot) {
    extern __shared__ __align__(16) unsigned char sm[];
    const uint32_t smb = cvta_smem(sm);
    const int tid = threadIdx.x;
    const int wid = tid >> 5;
    const int l   = tid & 31;

    const int t   = blockIdx.z;
    const int OY0 = blockIdx.y * 4;
    const int OX0 = blockIdx.x * 16;

    // ---- Halo build: [ly 6][lx 18][32] s8, unit u swizzled by (lx>>2)&1 ----
    const signed char* spb = g_spk1s8 + (size_t)t * HP * WP * 32;
    if (tid < 216) {
        int u  = tid & 1;
        int px = tid >> 1;               // 0..107
        int ly = px / 18, lx = px - ly * 18;
        const signed char* src = spb + ((size_t)(OY0 + ly) * WP + OX0 + lx) * 32 + u * 16;
        uint32_t dst = smb + (ly * 18 + lx) * 32 + (u ^ ((lx >> 2) & 1)) * 16;
        CP16(dst, src);
    }

    // ---- B pipeline prologue (each thread: 2x16B per stage) ----
    const uint4* bsrc = g_Bf2s + tid;                 // + s*512, + 256
    const uint32_t bd0 = smb + SB_OFF + tid * 16;
    const uint32_t bd1 = bd0 + 256 * 16;

    CP16(bd0, bsrc);         CP16(bd1, bsrc + 256);        // s=0 -> stage 0
    CP_COMMIT();                                           // g0 = halo + B0
    CP16(bd0 + SB_STG, bsrc + 512); CP16(bd1 + SB_STG, bsrc + 768);
    CP_COMMIT();                                           // g1 = B1

    const int mt = wid & 3;
    const int nh = wid >> 2;

    const int pxl   = ((l >> 3) & 1) * 8 + (l & 7);   // fragment row = px
    const int uhalf = (l >> 4) & 1;

    int c[15][4];
#pragma unroll
    for (int nt = 0; nt < 15; nt++)
#pragma unroll
        for (int j = 0; j < 4; j++) c[nt][j] = 0;

    int stage = 0;
    for (int s = 0; s < 9; s++) {
        if (s < 8) { CP_WAIT(1); } else { CP_WAIT(0); }
        __syncthreads();
        if (s + 2 < 9) {
            int st2 = stage + 2; if (st2 >= 3) st2 -= 3;
            CP16(bd0 + st2 * SB_STG, bsrc + (size_t)(s + 2) * 512);
            CP16(bd1 + st2 * SB_STG, bsrc + (size_t)(s + 2) * 512 + 256);
            CP_COMMIT();
        }

        int kh = (s >= 6) ? 2 : (s >= 3 ? 1 : 0);
        int kw = s - 3 * kh;
        int x  = pxl + kw;
        uint32_t addr = smb + ((mt + kh) * 18 + x) * 32
                      + (uhalf ^ ((x >> 2) & 1)) * 16;
        uint32_t a0, a1, a2, a3;
        asm volatile("ldmatrix.sync.aligned.m8n8.x4.shared.b16 {%0,%1,%2,%3}, [%4];"
                     : "=r"(a0), "=r"(a1), "=r"(a2), "=r"(a3) : "r"(addr));

        const uint32_t bs = smb + SB_OFF + stage * SB_STG + (nh * 256 + l) * 16;
#pragma unroll
        for (int jp = 0; jp < 8; jp++) {
            uint4 b = *(const uint4*)(sm + (bs - smb) + jp * 512);
            asm volatile(
                "mma.sync.aligned.m16n8k32.row.col.s32.s8.s8.s32 "
                "{%0,%1,%2,%3}, {%4,%5,%6,%7}, {%8,%9}, {%0,%1,%2,%3};"
                : "+r"(c[2*jp][0]), "+r"(c[2*jp][1]),
                  "+r"(c[2*jp][2]), "+r"(c[2*jp][3])
                : "r"(a0), "r"(a1), "r"(a2), "r"(a3), "r"(b.x), "r"(b.y));
            if (jp < 7) {
                asm volatile(
                    "mma.sync.aligned.m16n8k32.row.col.s32.s8.s8.s32 "
                    "{%0,%1,%2,%3}, {%4,%5,%6,%7}, {%8,%9}, {%0,%1,%2,%3};"
                    : "+r"(c[2*jp+1][0]), "+r"(c[2*jp+1][1]),
                      "+r"(c[2*jp+1][2]), "+r"(c[2*jp+1][3])
                    : "r"(a0), "r"(a1), "r"(a2), "r"(a3), "r"(b.z), "r"(b.w));
            }
        }
        stage++; if (stage == 3) stage = 0;
    }

    // ---- Epilogue: fire(10) on integer accum, scatter stores ----
    const int g   = l >> 2;
    const int tig = l & 3;
    const int y   = OY0 + mt;
    const size_t tb = (size_t)t * C2O * HO * WO + (size_t)y * WO + OX0;

#pragma unroll
    for (int nt = 0; nt < 15; nt++) {
        int oc0 = nh * 120 + nt * 8 + 2 * tig;
#pragma unroll
        for (int j = 0; j < 4; j++) {
            int   oc = oc0 + (j & 1);
            int   xx = g + ((j & 2) ? 8 : 0);
            int   v  = c[nt][j];
            float pv = (v > THR_C) ? (float)v * INV_WS : 0.0f;
            float sv = (v > THR_C) ? 1.0f : 0.0f;
            size_t bi = tb + (size_t)oc * HO * WO + xx;
            spk[bi] = sv;
            pot[bi] = pv;
        }
    }
}

// ---------------------------------------------------------------------------
extern "C" void kernel_launch(void* const* d_in, const int* in_sizes, int n_in,
                              void* d_out, int out_size) {
    const float* in = (const float*)d_in[0];
    const float* w1 = (const float*)d_in[1];
    const float* w2 = (const float*)d_in[2];

    float* spk = (float*)d_out;
    const size_t n2 = (size_t)TT * C2O * HO * WO;
    float* pot = spk + n2;

    void* p1 = nullptr; cudaGetSymbolAddress(&p1, g_spk1s8);
    cudaMemsetAsync(p1, 0, (size_t)TT * HP * WP * 32, 0);

    cudaFuncSetAttribute(k_conv1, cudaFuncAttributeMaxDynamicSharedMemorySize, C1_SMEM);
    cudaFuncSetAttribute(k_conv2, cudaFuncAttributeMaxDynamicSharedMemorySize, SM2_TOT);

    const int nprep = 13 * 2 * 32 + 9 * 2 * 8 * 32;
    k_prep<<<(nprep + 255) / 256, 256>>>(w1, w2);
    k_cvt<<<(TT * HI * WI + 255) / 256, 256>>>(in);
    k_conv1<<<dim3(14, 14, TT), 256, C1_SMEM>>>();
    k_conv2<<<dim3(7, 28, TT), 256, SM2_TOT>>>(spk, pot);
}

// round 14
// speedup vs baseline: 1.3480x; 1.3480x over previous
#include <cuda_runtime.h>
#include <cuda_bf16.h>
#include <cstdint>

#define TT  15
#define C1I 6
#define HI  224
#define WI  224
#define C1O 30
#define HP  114
#define WP  114
#define C2O 240
#define HO  112
#define WO  112

// Input, channel-last bf16: [t][y(224)][x(224)][8]
__device__ __align__(16) unsigned short g_inb[(size_t)TT * HI * WI * 8];
// Layer-1 pooled spikes, channel-last bf16, padded: [t][y(114)][x(114)][32]
__device__ __align__(16) unsigned short g_spk1b[(size_t)TT * HP * WP * 32];
// Conv1 B-fragments, nt-paired: [s(13)][jp(2)][lane(32)] uint4
__device__ __align__(16) uint4 g_Bf1p[13 * 2 * 32];
// Conv2 B-fragments, nq-quartered: [s(18)][nq(4)][jp(4)][lane(32)] uint4
// (oc = nq*64 + nt*8 + n; nt = 2*jp+h; oc >= 240 zero-padded)
__device__ __align__(16) uint4 g_Bf2q[18 * 4 * 4 * 32];

__device__ __forceinline__ uint32_t cvta_smem(const void* p) {
    uint32_t a;
    asm("{ .reg .u64 t; cvta.to.shared.u64 t, %1; cvt.u32.u64 %0, t; }"
        : "=r"(a) : "l"(p));
    return a;
}
__device__ __forceinline__ unsigned short f2bf(float f) {
    __nv_bfloat16 b = __float2bfloat16(f);
    return *(unsigned short*)&b;
}

#define CP16(dst, src) \
    asm volatile("cp.async.cg.shared.global [%0], [%1], 16;" \
                 :: "r"(dst), "l"(src) : "memory")
#define CP16Z(dst, src, sz) \
    asm volatile("cp.async.cg.shared.global [%0], [%1], 16, %2;" \
                 :: "r"(dst), "l"(src), "r"(sz) : "memory")
#define CP_COMMIT() asm volatile("cp.async.commit_group;" ::: "memory")
#define CP_WAIT(n)  asm volatile("cp.async.wait_group %0;" :: "n"(n) : "memory")

#define MMA16816(c, a0, a1, a2, a3, b0, b1) \
    asm volatile( \
        "mma.sync.aligned.m16n8k16.row.col.f32.bf16.bf16.f32 " \
        "{%0,%1,%2,%3}, {%4,%5,%6,%7}, {%8,%9}, {%0,%1,%2,%3};" \
        : "+f"((c)[0]), "+f"((c)[1]), "+f"((c)[2]), "+f"((c)[3]) \
        : "r"(a0), "r"(a1), "r"(a2), "r"(a3), "r"(b0), "r"(b1))

// ---------------------------------------------------------------------------
// Prep: B-fragments (m16n8k16 .row.col: lane l holds n=l>>2, k=(l&3)*2+r*8+e).
// ---------------------------------------------------------------------------
__global__ __launch_bounds__(256) void k_prep(const float* __restrict__ w1,
                                              const float* __restrict__ w2) {
    int i = blockIdx.x * 256 + threadIdx.x;
    if (i < 13 * 2 * 32) {                       // conv1: k = tap*8+ic
        int l = i & 31, jp = (i >> 5) & 1, s = i >> 6;
        uint32_t q[4];
#pragma unroll
        for (int h = 0; h < 2; h++) {
            int nt = 2 * jp + h;
            int oc = nt * 8 + (l >> 2);
#pragma unroll
            for (int r = 0; r < 2; r++) {
                uint32_t pk = 0;
#pragma unroll
                for (int e = 0; e < 2; e++) {
                    int k = s * 16 + (l & 3) * 2 + r * 8 + e;
                    int tap = k >> 3, ic = k & 7;
                    float w = (ic < 6 && tap < 25 && oc < 30)
                            ? w1[(oc * 6 + ic) * 25 + tap] : 0.0f;
                    pk |= (uint32_t)f2bf(w) << (16 * e);
                }
                q[h * 2 + r] = pk;
            }
        }
        g_Bf1p[i] = make_uint4(q[0], q[1], q[2], q[3]);
    } else if (i < 13 * 2 * 32 + 18 * 4 * 4 * 32) {   // conv2: k = tap*32+ic
        int j = i - 13 * 2 * 32;
        int l = j & 31, jp = (j >> 5) & 3, nq = (j >> 7) & 3, s = j >> 9;
        uint32_t q[4] = {0, 0, 0, 0};
#pragma unroll
        for (int h = 0; h < 2; h++) {
            int nt = 2 * jp + h;
            int oc = nq * 64 + nt * 8 + (l >> 2);
            if (oc < 240) {
#pragma unroll
                for (int r = 0; r < 2; r++) {
                    uint32_t pk = 0;
#pragma unroll
                    for (int e = 0; e < 2; e++) {
                        int k = s * 16 + (l & 3) * 2 + r * 8 + e;
                        int tap = k >> 5, ic = k & 31;
                        float w = (ic < 30) ? w2[(oc * 30 + ic) * 9 + tap] : 0.0f;
                        pk |= (uint32_t)f2bf(w) << (16 * e);
                    }
                    q[h * 2 + r] = pk;
                }
            }
        }
        g_Bf2q[j] = make_uint4(q[0], q[1], q[2], q[3]);
    }
}

// ---------------------------------------------------------------------------
// Convert input NCHW f32 -> channel-last bf16 (coalesced both sides).
// ---------------------------------------------------------------------------
__global__ __launch_bounds__(256) void k_cvt(const float* __restrict__ in) {
    int p = blockIdx.x * 256 + threadIdx.x;
    if (p >= TT * HI * WI) return;
    int t  = p / (HI * WI);
    int px = p % (HI * WI);
    const float* b = in + (size_t)t * C1I * HI * WI + px;
    unsigned short r[8];
#pragma unroll
    for (int ic = 0; ic < 6; ic++) r[ic] = f2bf(b[(size_t)ic * HI * WI]);
    r[6] = 0; r[7] = 0;
    *(uint4*)(g_inb + (size_t)p * 8) = *(uint4*)r;
}

// ---------------------------------------------------------------------------
// Kernel 1: conv1 via mma.sync + fire(15) + maxpool 2x2 -> channel-last bf16.
// CTA (256 thr, 8 warps): 16x16 conv-px tile (M=256), N=32, K=208.
// ---------------------------------------------------------------------------
#define C1_IMG   0
#define C1_C     6400
#define C1_SMEM  (6400 + 32768)

__global__ __launch_bounds__(256) void k_conv1() {
    extern __shared__ __align__(16) unsigned char sm[];
    const uint32_t smb = cvta_smem(sm);
    float* sC = (float*)(sm + C1_C);           // [py16][px16][oc32]

    const int t   = blockIdx.z;
    const int X0  = blockIdx.x * 16;
    const int Y0  = blockIdx.y * 16;
    const int tid = threadIdx.x;
    const int wid = tid >> 5;
    const int l   = tid & 31;

    const unsigned short* inb = g_inb + (size_t)t * HI * WI * 8;
    for (int i = tid; i < 400; i += 256) {
        int ly = i / 20, lx = i % 20;
        int gy = Y0 - 2 + ly, gx = X0 - 2 + lx;
        bool ok = (unsigned)gy < (unsigned)HI && (unsigned)gx < (unsigned)WI;
        int cy = ok ? gy : 0, cx = ok ? gx : 0;
        const unsigned short* src = inb + ((size_t)cy * WI + cx) * 8;
        CP16Z(smb + C1_IMG + i * 16, src, ok ? 16 : 0);
    }
    CP_COMMIT();
    CP_WAIT(0);
    __syncthreads();

    float c[2][4][4];
#pragma unroll
    for (int i = 0; i < 2; i++)
#pragma unroll
        for (int nt = 0; nt < 4; nt++)
#pragma unroll
            for (int j = 0; j < 4; j++) c[i][nt][j] = 0.0f;

    const int pxl  = l & 15;
    const int tsel = l >> 4;

    for (int s = 0; s < 13; s++) {
        int tp = 2 * s + tsel; if (tp > 24) tp = 24;   // tap25: w=0, clamp addr
        int kh = tp / 5, kw = tp - 5 * kh;
#pragma unroll
        for (int i = 0; i < 2; i++) {
            int py = 2 * wid + i;
            uint32_t addr = smb + C1_IMG + ((py + kh) * 20 + pxl + kw) * 16;
            uint32_t a0, a1, a2, a3;
            asm volatile("ldmatrix.sync.aligned.m8n8.x4.shared.b16 {%0,%1,%2,%3}, [%4];"
                         : "=r"(a0), "=r"(a1), "=r"(a2), "=r"(a3) : "r"(addr));
            const uint4* bp = g_Bf1p + s * 64 + l;
#pragma unroll
            for (int jp = 0; jp < 2; jp++) {
                uint4 b = __ldg(bp + jp * 32);
                MMA16816(c[i][2*jp],   a0, a1, a2, a3, b.x, b.y);
                MMA16816(c[i][2*jp+1], a0, a1, a2, a3, b.z, b.w);
            }
        }
    }

#pragma unroll
    for (int i = 0; i < 2; i++) {
        int py = 2 * wid + i;
        int px0 = l >> 2, oc0 = 2 * (l & 3);
#pragma unroll
        for (int nt = 0; nt < 4; nt++) {
            *(float2*)(sC + (py * 16 + px0) * 32 + nt * 8 + oc0)
                = make_float2(c[i][nt][0], c[i][nt][1]);
            *(float2*)(sC + (py * 16 + px0 + 8) * 32 + nt * 8 + oc0)
                = make_float2(c[i][nt][2], c[i][nt][3]);
        }
    }
    __syncthreads();

    {
        int ocq = tid & 3;
        int ppx = (tid >> 2) & 7;
        int ppy = tid >> 5;
        uint32_t w[4];
#pragma unroll
        for (int u = 0; u < 4; u++) {
            uint32_t word = 0;
#pragma unroll
            for (int h = 0; h < 2; h++) {
                int oc = ocq * 8 + u * 2 + h;
                const float* p = sC + ((2 * ppy) * 16 + 2 * ppx) * 32 + oc;
                float m = fmaxf(fmaxf(p[0], p[32]), fmaxf(p[16 * 32], p[17 * 32]));
                if (m > 15.0f) word |= 0x3F80u << (16 * h);
            }
            w[u] = word;
        }
        int y = blockIdx.y * 8 + ppy + 1;
        int x = blockIdx.x * 8 + ppx + 1;
        *(uint4*)(g_spk1b + ((size_t)(t * HP + y) * WP + x) * 32 + ocq * 8)
            = make_uint4(w[0], w[1], w[2], w[3]);
    }
}

// ---------------------------------------------------------------------------
// Kernel 2: conv2 via mma.sync + fire(10). CTA (512 thr, 16 warps = 4mt x 4nq):
// 16x8 px (M=128), N=256 (240 + pad). Warp tile M32 x N64: 2 ldmatrix +
// 4 B-LDS.128 -> 16 mma per k-step (1.5 L1-wf/mma). 3-stage cp.async B pipe.
// ---------------------------------------------------------------------------
#define ASTR   592
#define SB_OFF (128 * ASTR)            // 75776
#define SB_STG 8192
#define SMA_BYTES (SB_OFF + 3 * SB_STG)

__global__ __launch_bounds__(512) void k_conv2(float* __restrict__ spk,
                                               float* __restrict__ pot) {
    extern __shared__ __align__(16) unsigned char sm[];
    const uint32_t smb = cvta_smem(sm);
    const int tid = threadIdx.x;
    const int wid = tid >> 5;
    const int l   = tid & 31;

    const int t   = blockIdx.z;
    const int OY0 = blockIdx.y * 8;
    const int OX0 = blockIdx.x * 16;

    // ---- A build via cp.async (9 x 16B per thread) ----
    const unsigned short* spb = g_spk1b + (size_t)t * HP * WP * 32;
    for (int i = tid; i < 4608; i += 512) {
        int u = i & 3, tap = (i >> 2) % 9, m = i / 36;
        int kh = tap / 3, kw = tap - kh * 3;
        int py = m >> 4, px = m & 15;
        const unsigned short* src = spb +
            ((size_t)(OY0 + py + kh) * WP + (OX0 + px + kw)) * 32 + u * 8;
        CP16(smb + m * ASTR + tap * 64 + u * 16, src);
    }

    // ---- B pipeline prologue: one uint4 per thread per stage ----
    const uint4* bsrc0 = g_Bf2q + tid;        // step s at + s*512
    const uint32_t bdst = smb + SB_OFF + tid * 16;

    CP16(bdst, bsrc0);                        // s = 0 -> stage 0
    CP_COMMIT();                              // g0 = A + B0
    CP16(bdst + SB_STG, bsrc0 + 512);         // s = 1 -> stage 1
    CP_COMMIT();                              // g1 = B1

    const int mt = wid & 3;
    const int nq = wid >> 2;

    const uint32_t abase0 = smb
        + (mt * 32 + ((l >> 3) & 1) * 8 + (l & 7)) * ASTR
        + ((l >> 4) & 1) * 16;
    const uint32_t abase1 = abase0 + 16 * ASTR;
    const uint32_t boff = SB_OFF + (nq * 128 + l) * 16;   // byte offset in sm[]

    float c[2][8][4];
#pragma unroll
    for (int mi = 0; mi < 2; mi++)
#pragma unroll
        for (int nt = 0; nt < 8; nt++)
#pragma unroll
            for (int j = 0; j < 4; j++) c[mi][nt][j] = 0.0f;

    int stage = 0;
    for (int s = 0; s < 18; s++) {
        if (s < 17) { CP_WAIT(1); } else { CP_WAIT(0); }
        __syncthreads();
        if (s + 2 < 18) {
            int st2 = stage + 2; if (st2 >= 3) st2 -= 3;
            CP16(bdst + st2 * SB_STG, bsrc0 + (size_t)(s + 2) * 512);
            CP_COMMIT();
        }

        uint32_t a[2][4];
        asm volatile("ldmatrix.sync.aligned.m8n8.x4.shared.b16 {%0,%1,%2,%3}, [%4];"
                     : "=r"(a[0][0]), "=r"(a[0][1]), "=r"(a[0][2]), "=r"(a[0][3])
                     : "r"(abase0 + s * 32));
        asm volatile("ldmatrix.sync.aligned.m8n8.x4.shared.b16 {%0,%1,%2,%3}, [%4];"
                     : "=r"(a[1][0]), "=r"(a[1][1]), "=r"(a[1][2]), "=r"(a[1][3])
                     : "r"(abase1 + s * 32));

        const unsigned char* bsm = sm + boff + stage * SB_STG;
#pragma unroll
        for (int jp = 0; jp < 4; jp++) {
            uint4 b = *(const uint4*)(bsm + jp * 512);
#pragma unroll
            for (int mi = 0; mi < 2; mi++) {
                MMA16816(c[mi][2*jp],   a[mi][0], a[mi][1], a[mi][2], a[mi][3], b.x, b.y);
                MMA16816(c[mi][2*jp+1], a[mi][0], a[mi][1], a[mi][2], a[mi][3], b.z, b.w);
            }
        }
        stage++; if (stage == 3) stage = 0;
    }

    // ---- Epilogue: fire(10), scatter stores (R8-proven form) ----
    const int g   = l >> 2;
    const int tig = l & 3;
    const size_t tb = (size_t)t * C2O * HO * WO;
    const size_t n2 = (size_t)TT * C2O * HO * WO;

#pragma unroll
    for (int mi = 0; mi < 2; mi++) {
#pragma unroll
        for (int nt = 0; nt < 8; nt++) {
            int oc0 = nq * 64 + nt * 8 + 2 * tig;
            if (oc0 >= 240) continue;                  // N padding
#pragma unroll
            for (int j = 0; j < 4; j++) {
                int   oc = oc0 + (j & 1);
                int   m  = mt * 32 + mi * 16 + g + ((j & 2) ? 8 : 0);
                int   yy = OY0 + (m >> 4);
                int   xx = OX0 + (m & 15);
                float a  = c[mi][nt][j];
                size_t bi = tb + ((size_t)oc * HO + yy) * WO + xx;
                spk[bi]      = a > 10.0f ? 1.0f : 0.0f;
                spk[bi + n2] = a > 10.0f ? a : 0.0f;
            }
        }
    }
}

// ---------------------------------------------------------------------------
extern "C" void kernel_launch(void* const* d_in, const int* in_sizes, int n_in,
                              void* d_out, int out_size) {
    const float* in = (const float*)d_in[0];
    const float* w1 = (const float*)d_in[1];
    const float* w2 = (const float*)d_in[2];

    float* spk = (float*)d_out;
    const size_t n2 = (size_t)TT * C2O * HO * WO;
    float* pot = spk + n2;

    void* p1 = nullptr; cudaGetSymbolAddress(&p1, g_spk1b);
    cudaMemsetAsync(p1, 0, (size_t)TT * HP * WP * 32 * 2, 0);

    cudaFuncSetAttribute(k_conv1, cudaFuncAttributeMaxDynamicSharedMemorySize, C1_SMEM);
    cudaFuncSetAttribute(k_conv2, cudaFuncAttributeMaxDynamicSharedMemorySize, SMA_BYTES);

    const int nprep = 13 * 2 * 32 + 18 * 4 * 4 * 32;
    k_prep<<<(nprep + 255) / 256, 256>>>(w1, w2);
    k_cvt<<<(TT * HI * WI + 255) / 256, 256>>>(in);
    k_conv1<<<dim3(14, 14, TT), 256, C1_SMEM>>>();
    k_conv2<<<dim3(7, 14, TT), 512, SMA_BYTES>>>(spk, pot);
}

// round 15
// speedup vs baseline: 1.4618x; 1.0845x over previous
#include <cuda_runtime.h>
#include <cuda_bf16.h>
#include <cstdint>

#define TT  15
#define C1I 6
#define HI  224
#define WI  224
#define C1O 30
#define HP  114
#define WP  114
#define C2O 240
#define HO  112
#define WO  112

// Input, channel-last bf16: [t][y(224)][x(224)][8]
__device__ __align__(16) unsigned short g_inb[(size_t)TT * HI * WI * 8];
// Layer-1 pooled spikes, channel-last bf16, padded: [t][y(114)][x(114)][32]
__device__ __align__(16) unsigned short g_spk1b[(size_t)TT * HP * WP * 32];
// Conv1 B-fragments, nt-paired: [s(13)][jp(2)][lane(32)] uint4
__device__ __align__(16) uint4 g_Bf1p[13 * 2 * 32];
// Conv2 B-fragments, nq-quartered: [s(18)][nq(4)][jp(4)][lane(32)] uint4
__device__ __align__(16) uint4 g_Bf2q[18 * 4 * 4 * 32];

__device__ __forceinline__ uint32_t cvta_smem(const void* p) {
    uint32_t a;
    asm("{ .reg .u64 t; cvta.to.shared.u64 t, %1; cvt.u32.u64 %0, t; }"
        : "=r"(a) : "l"(p));
    return a;
}
__device__ __forceinline__ unsigned short f2bf(float f) {
    __nv_bfloat16 b = __float2bfloat16(f);
    return *(unsigned short*)&b;
}

#define CP16(dst, src) \
    asm volatile("cp.async.cg.shared.global [%0], [%1], 16;" \
                 :: "r"(dst), "l"(src) : "memory")
#define CP16Z(dst, src, sz) \
    asm volatile("cp.async.cg.shared.global [%0], [%1], 16, %2;" \
                 :: "r"(dst), "l"(src), "r"(sz) : "memory")
#define CP_COMMIT() asm volatile("cp.async.commit_group;" ::: "memory")
#define CP_WAIT(n)  asm volatile("cp.async.wait_group %0;" :: "n"(n) : "memory")

#define MMA16816(c, a0, a1, a2, a3, b0, b1) \
    asm volatile( \
        "mma.sync.aligned.m16n8k16.row.col.f32.bf16.bf16.f32 " \
        "{%0,%1,%2,%3}, {%4,%5,%6,%7}, {%8,%9}, {%0,%1,%2,%3};" \
        : "+f"((c)[0]), "+f"((c)[1]), "+f"((c)[2]), "+f"((c)[3]) \
        : "r"(a0), "r"(a1), "r"(a2), "r"(a3), "r"(b0), "r"(b1))

// ---------------------------------------------------------------------------
// Prep: B-fragments (m16n8k16 .row.col: lane l holds n=l>>2, k=(l&3)*2+r*8+e).
// ---------------------------------------------------------------------------
__global__ __launch_bounds__(256) void k_prep(const float* __restrict__ w1,
                                              const float* __restrict__ w2) {
    int i = blockIdx.x * 256 + threadIdx.x;
    if (i < 13 * 2 * 32) {                       // conv1: k = tap*8+ic
        int l = i & 31, jp = (i >> 5) & 1, s = i >> 6;
        uint32_t q[4];
#pragma unroll
        for (int h = 0; h < 2; h++) {
            int nt = 2 * jp + h;
            int oc = nt * 8 + (l >> 2);
#pragma unroll
            for (int r = 0; r < 2; r++) {
                uint32_t pk = 0;
#pragma unroll
                for (int e = 0; e < 2; e++) {
                    int k = s * 16 + (l & 3) * 2 + r * 8 + e;
                    int tap = k >> 3, ic = k & 7;
                    float w = (ic < 6 && tap < 25 && oc < 30)
                            ? w1[(oc * 6 + ic) * 25 + tap] : 0.0f;
                    pk |= (uint32_t)f2bf(w) << (16 * e);
                }
                q[h * 2 + r] = pk;
            }
        }
        g_Bf1p[i] = make_uint4(q[0], q[1], q[2], q[3]);
    } else if (i < 13 * 2 * 32 + 18 * 4 * 4 * 32) {   // conv2: k = tap*32+ic
        int j = i - 13 * 2 * 32;
        int l = j & 31, jp = (j >> 5) & 3, nq = (j >> 7) & 3, s = j >> 9;
        uint32_t q[4] = {0, 0, 0, 0};
#pragma unroll
        for (int h = 0; h < 2; h++) {
            int nt = 2 * jp + h;
            int oc = nq * 64 + nt * 8 + (l >> 2);
            if (oc < 240) {
#pragma unroll
                for (int r = 0; r < 2; r++) {
                    uint32_t pk = 0;
#pragma unroll
                    for (int e = 0; e < 2; e++) {
                        int k = s * 16 + (l & 3) * 2 + r * 8 + e;
                        int tap = k >> 5, ic = k & 31;
                        float w = (ic < 30) ? w2[(oc * 30 + ic) * 9 + tap] : 0.0f;
                        pk |= (uint32_t)f2bf(w) << (16 * e);
                    }
                    q[h * 2 + r] = pk;
                }
            }
        }
        g_Bf2q[j] = make_uint4(q[0], q[1], q[2], q[3]);
    }
}

// ---------------------------------------------------------------------------
// Convert input NCHW f32 -> channel-last bf16 (coalesced both sides).
// ---------------------------------------------------------------------------
__global__ __launch_bounds__(256) void k_cvt(const float* __restrict__ in) {
    int p = blockIdx.x * 256 + threadIdx.x;
    if (p >= TT * HI * WI) return;
    int t  = p / (HI * WI);
    int px = p % (HI * WI);
    const float* b = in + (size_t)t * C1I * HI * WI + px;
    unsigned short r[8];
#pragma unroll
    for (int ic = 0; ic < 6; ic++) r[ic] = f2bf(b[(size_t)ic * HI * WI]);
    r[6] = 0; r[7] = 0;
    *(uint4*)(g_inb + (size_t)p * 8) = *(uint4*)r;
}

// ---------------------------------------------------------------------------
// Kernel 1: conv1 via mma.sync + fire(15) + maxpool 2x2 -> channel-last bf16.
// CTA (256 thr, 8 warps): 16x16 conv-px tile (M=256), N=32, K=208.
// ---------------------------------------------------------------------------
#define C1_IMG   0
#define C1_C     6400
#define C1_SMEM  (6400 + 32768)

__global__ __launch_bounds__(256) void k_conv1() {
    extern __shared__ __align__(16) unsigned char sm[];
    const uint32_t smb = cvta_smem(sm);
    float* sC = (float*)(sm + C1_C);           // [py16][px16][oc32]

    const int t   = blockIdx.z;
    const int X0  = blockIdx.x * 16;
    const int Y0  = blockIdx.y * 16;
    const int tid = threadIdx.x;
    const int wid = tid >> 5;
    const int l   = tid & 31;

    const unsigned short* inb = g_inb + (size_t)t * HI * WI * 8;
    for (int i = tid; i < 400; i += 256) {
        int ly = i / 20, lx = i % 20;
        int gy = Y0 - 2 + ly, gx = X0 - 2 + lx;
        bool ok = (unsigned)gy < (unsigned)HI && (unsigned)gx < (unsigned)WI;
        int cy = ok ? gy : 0, cx = ok ? gx : 0;
        const unsigned short* src = inb + ((size_t)cy * WI + cx) * 8;
        CP16Z(smb + C1_IMG + i * 16, src, ok ? 16 : 0);
    }
    CP_COMMIT();
    CP_WAIT(0);
    __syncthreads();

    float c[2][4][4];
#pragma unroll
    for (int i = 0; i < 2; i++)
#pragma unroll
        for (int nt = 0; nt < 4; nt++)
#pragma unroll
            for (int j = 0; j < 4; j++) c[i][nt][j] = 0.0f;

    const int pxl  = l & 15;
    const int tsel = l >> 4;

    for (int s = 0; s < 13; s++) {
        int tp = 2 * s + tsel; if (tp > 24) tp = 24;   // tap25: w=0, clamp addr
        int kh = tp / 5, kw = tp - 5 * kh;
#pragma unroll
        for (int i = 0; i < 2; i++) {
            int py = 2 * wid + i;
            uint32_t addr = smb + C1_IMG + ((py + kh) * 20 + pxl + kw) * 16;
            uint32_t a0, a1, a2, a3;
            asm volatile("ldmatrix.sync.aligned.m8n8.x4.shared.b16 {%0,%1,%2,%3}, [%4];"
                         : "=r"(a0), "=r"(a1), "=r"(a2), "=r"(a3) : "r"(addr));
            const uint4* bp = g_Bf1p + s * 64 + l;
#pragma unroll
            for (int jp = 0; jp < 2; jp++) {
                uint4 b = __ldg(bp + jp * 32);
                MMA16816(c[i][2*jp],   a0, a1, a2, a3, b.x, b.y);
                MMA16816(c[i][2*jp+1], a0, a1, a2, a3, b.z, b.w);
            }
        }
    }

#pragma unroll
    for (int i = 0; i < 2; i++) {
        int py = 2 * wid + i;
        int px0 = l >> 2, oc0 = 2 * (l & 3);
#pragma unroll
        for (int nt = 0; nt < 4; nt++) {
            *(float2*)(sC + (py * 16 + px0) * 32 + nt * 8 + oc0)
                = make_float2(c[i][nt][0], c[i][nt][1]);
            *(float2*)(sC + (py * 16 + px0 + 8) * 32 + nt * 8 + oc0)
                = make_float2(c[i][nt][2], c[i][nt][3]);
        }
    }
    __syncthreads();

    {
        int ocq = tid & 3;
        int ppx = (tid >> 2) & 7;
        int ppy = tid >> 5;
        uint32_t w[4];
#pragma unroll
        for (int u = 0; u < 4; u++) {
            uint32_t word = 0;
#pragma unroll
            for (int h = 0; h < 2; h++) {
                int oc = ocq * 8 + u * 2 + h;
                const float* p = sC + ((2 * ppy) * 16 + 2 * ppx) * 32 + oc;
                float m = fmaxf(fmaxf(p[0], p[32]), fmaxf(p[16 * 32], p[17 * 32]));
                if (m > 15.0f) word |= 0x3F80u << (16 * h);
            }
            w[u] = word;
        }
        int y = blockIdx.y * 8 + ppy + 1;
        int x = blockIdx.x * 8 + ppx + 1;
        *(uint4*)(g_spk1b + ((size_t)(t * HP + y) * WP + x) * 32 + ocq * 8)
            = make_uint4(w[0], w[1], w[2], w[3]);
    }
}

// ---------------------------------------------------------------------------
// Kernel 2: conv2 via mma.sync + fire(10), NO im2col.
// CTA (256 thr, 8 warps = 2mt x 4nq): M=64 (4py x 16px), N=256.
// A: raw halo [6][18] px x 80B (64B data + 16 pad; 5*px mod 8 -> conflict-free
// ldmatrix). k16 step s: tap = s>>1 (kh,kw shift), h = s&1 (channel half).
// B: 3-stage cp.async pipeline. 2 CTAs/SM.
// ---------------------------------------------------------------------------
#define HSTR   80
#define SB2    (6 * 18 * HSTR)         // 8640
#define SB_STG 8192
#define SM2_BYTES (SB2 + 3 * SB_STG)   // 33216

__global__ __launch_bounds__(256, 2) void k_conv2(float* __restrict__ spk,
                                                  float* __restrict__ pot) {
    extern __shared__ __align__(16) unsigned char sm[];
    const uint32_t smb = cvta_smem(sm);
    const int tid = threadIdx.x;
    const int wid = tid >> 5;
    const int l   = tid & 31;

    const int t   = blockIdx.z;
    const int OY0 = blockIdx.y * 4;
    const int OX0 = blockIdx.x * 16;

    // ---- Halo build: 108 px x 4 x 16B cp.async ----
    const unsigned short* spb = g_spk1b + (size_t)t * HP * WP * 32;
    for (int i = tid; i < 432; i += 256) {
        int u = i & 3, px = i >> 2;
        int ly = px / 18, lx = px - ly * 18;
        const unsigned short* src = spb + ((size_t)(OY0 + ly) * WP + OX0 + lx) * 32 + u * 8;
        CP16(smb + (ly * 18 + lx) * HSTR + u * 16, src);
    }

    // ---- B pipeline prologue: two uint4 per thread per stage ----
    const uint4* bsrc0 = g_Bf2q + tid;        // step s at + s*512; second half +256
    const uint32_t bdst0 = smb + SB2 + tid * 16;
    const uint32_t bdst1 = bdst0 + 256 * 16;

    CP16(bdst0, bsrc0);  CP16(bdst1, bsrc0 + 256);           // s=0 -> stage 0
    CP_COMMIT();                                             // g0 = halo + B0
    CP16(bdst0 + SB_STG, bsrc0 + 512);  CP16(bdst1 + SB_STG, bsrc0 + 768);
    CP_COMMIT();                                             // g1 = B1

    const int mt = wid & 1;                   // 2 mt x 4 nq
    const int nq = wid >> 1;

    const int pxl   = (l & 7) + ((l >> 3) & 1) * 8;   // matrix row = px
    const int khalf = (l >> 4) & 1;
    const uint32_t boff = SB2 + (nq * 128 + l) * 16;

    float c[2][8][4];
#pragma unroll
    for (int mi = 0; mi < 2; mi++)
#pragma unroll
        for (int nt = 0; nt < 8; nt++)
#pragma unroll
            for (int j = 0; j < 4; j++) c[mi][nt][j] = 0.0f;

    int stage = 0;
    for (int s = 0; s < 18; s++) {
        if (s < 17) { CP_WAIT(1); } else { CP_WAIT(0); }
        __syncthreads();
        if (s + 2 < 18) {
            int st2 = stage + 2; if (st2 >= 3) st2 -= 3;
            CP16(bdst0 + st2 * SB_STG, bsrc0 + (size_t)(s + 2) * 512);
            CP16(bdst1 + st2 * SB_STG, bsrc0 + (size_t)(s + 2) * 512 + 256);
            CP_COMMIT();
        }

        int tap = s >> 1, h = s & 1;
        int kh = (tap >= 6) ? 2 : (tap >= 3 ? 1 : 0);
        int kw = tap - 3 * kh;

        uint32_t a[2][4];
#pragma unroll
        for (int mi = 0; mi < 2; mi++) {
            int py = mt * 2 + mi;
            uint32_t addr = smb + ((py + kh) * 18 + pxl + kw) * HSTR
                          + h * 32 + khalf * 16;
            asm volatile("ldmatrix.sync.aligned.m8n8.x4.shared.b16 {%0,%1,%2,%3}, [%4];"
                         : "=r"(a[mi][0]), "=r"(a[mi][1]), "=r"(a[mi][2]), "=r"(a[mi][3])
                         : "r"(addr));
        }

        const unsigned char* bsm = sm + boff + stage * SB_STG;
#pragma unroll
        for (int jp = 0; jp < 4; jp++) {
            uint4 b = *(const uint4*)(bsm + jp * 512);
#pragma unroll
            for (int mi = 0; mi < 2; mi++) {
                MMA16816(c[mi][2*jp],   a[mi][0], a[mi][1], a[mi][2], a[mi][3], b.x, b.y);
                MMA16816(c[mi][2*jp+1], a[mi][0], a[mi][1], a[mi][2], a[mi][3], b.z, b.w);
            }
        }
        stage++; if (stage == 3) stage = 0;
    }

    // ---- Epilogue: fire(10), scatter stores ----
    const int g   = l >> 2;
    const int tig = l & 3;
    const size_t tb = (size_t)t * C2O * HO * WO;
    const size_t n2 = (size_t)TT * C2O * HO * WO;

#pragma unroll
    for (int mi = 0; mi < 2; mi++) {
        int yy = OY0 + mt * 2 + mi;
#pragma unroll
        for (int nt = 0; nt < 8; nt++) {
            int oc0 = nq * 64 + nt * 8 + 2 * tig;
            if (oc0 >= 240) continue;                  // N padding
#pragma unroll
            for (int j = 0; j < 4; j++) {
                int   oc = oc0 + (j & 1);
                int   xx = OX0 + g + ((j & 2) ? 8 : 0);
                float a  = c[mi][nt][j];
                size_t bi = tb + ((size_t)oc * HO + yy) * WO + xx;
                spk[bi]      = a > 10.0f ? 1.0f : 0.0f;
                spk[bi + n2] = a > 10.0f ? a : 0.0f;
            }
        }
    }
}

// ---------------------------------------------------------------------------
extern "C" void kernel_launch(void* const* d_in, const int* in_sizes, int n_in,
                              void* d_out, int out_size) {
    const float* in = (const float*)d_in[0];
    const float* w1 = (const float*)d_in[1];
    const float* w2 = (const float*)d_in[2];

    float* spk = (float*)d_out;
    const size_t n2 = (size_t)TT * C2O * HO * WO;
    float* pot = spk + n2;

    void* p1 = nullptr; cudaGetSymbolAddress(&p1, g_spk1b);
    cudaMemsetAsync(p1, 0, (size_t)TT * HP * WP * 32 * 2, 0);

    cudaFuncSetAttribute(k_conv1, cudaFuncAttributeMaxDynamicSharedMemorySize, C1_SMEM);
    cudaFuncSetAttribute(k_conv2, cudaFuncAttributeMaxDynamicSharedMemorySize, SM2_BYTES);

    const int nprep = 13 * 2 * 32 + 18 * 4 * 4 * 32;
    k_prep<<<(nprep + 255) / 256, 256>>>(w1, w2);
    k_cvt<<<(TT * HI * WI + 255) / 256, 256>>>(in);
    k_conv1<<<dim3(14, 14, TT), 256, C1_SMEM>>>();
    k_conv2<<<dim3(7, 28, TT), 256, SM2_BYTES>>>(spk, pot);
}

// round 16
// speedup vs baseline: 1.5343x; 1.0495x over previous
#include <cuda_runtime.h>
#include <cuda_bf16.h>
#include <cstdint>

#define TT  15
#define C1I 6
#define HI  224
#define WI  224
#define C1O 30
#define HP  114
#define WP  114
#define C2O 240
#define HO  112
#define WO  112

// Input, channel-last bf16: [t][y(224)][x(224)][8]
__device__ __align__(16) unsigned short g_inb[(size_t)TT * HI * WI * 8];
// Layer-1 pooled spikes, channel-last bf16, padded: [t][y(114)][x(114)][32]
__device__ __align__(16) unsigned short g_spk1b[(size_t)TT * HP * WP * 32];
// Conv1 B-fragments, nt-paired: [s(13)][jp(2)][lane(32)] uint4
__device__ __align__(16) uint4 g_Bf1p[13 * 2 * 32];
// Conv2 B-fragments, nq-quartered: [s(18)][nq(4)][jp(4)][lane(32)] uint4
__device__ __align__(16) uint4 g_Bf2q[18 * 4 * 4 * 32];

__device__ __forceinline__ uint32_t cvta_smem(const void* p) {
    uint32_t a;
    asm("{ .reg .u64 t; cvta.to.shared.u64 t, %1; cvt.u32.u64 %0, t; }"
        : "=r"(a) : "l"(p));
    return a;
}
__device__ __forceinline__ unsigned short f2bf(float f) {
    __nv_bfloat16 b = __float2bfloat16(f);
    return *(unsigned short*)&b;
}

#define CP16(dst, src) \
    asm volatile("cp.async.cg.shared.global [%0], [%1], 16;" \
                 :: "r"(dst), "l"(src) : "memory")
#define CP16Z(dst, src, sz) \
    asm volatile("cp.async.cg.shared.global [%0], [%1], 16, %2;" \
                 :: "r"(dst), "l"(src), "r"(sz) : "memory")
#define CP_COMMIT() asm volatile("cp.async.commit_group;" ::: "memory")
#define CP_WAIT(n)  asm volatile("cp.async.wait_group %0;" :: "n"(n) : "memory")

#define MMA16816(c, a0, a1, a2, a3, b0, b1) \
    asm volatile( \
        "mma.sync.aligned.m16n8k16.row.col.f32.bf16.bf16.f32 " \
        "{%0,%1,%2,%3}, {%4,%5,%6,%7}, {%8,%9}, {%0,%1,%2,%3};" \
        : "+f"((c)[0]), "+f"((c)[1]), "+f"((c)[2]), "+f"((c)[3]) \
        : "r"(a0), "r"(a1), "r"(a2), "r"(a3), "r"(b0), "r"(b1))

// ---------------------------------------------------------------------------
// Prep: B-fragments (m16n8k16 .row.col: lane l holds n=l>>2, k=(l&3)*2+r*8+e).
// ---------------------------------------------------------------------------
__global__ __launch_bounds__(256) void k_prep(const float* __restrict__ w1,
                                              const float* __restrict__ w2) {
    int i = blockIdx.x * 256 + threadIdx.x;
    if (i < 13 * 2 * 32) {                       // conv1: k = tap*8+ic
        int l = i & 31, jp = (i >> 5) & 1, s = i >> 6;
        uint32_t q[4];
#pragma unroll
        for (int h = 0; h < 2; h++) {
            int nt = 2 * jp + h;
            int oc = nt * 8 + (l >> 2);
#pragma unroll
            for (int r = 0; r < 2; r++) {
                uint32_t pk = 0;
#pragma unroll
                for (int e = 0; e < 2; e++) {
                    int k = s * 16 + (l & 3) * 2 + r * 8 + e;
                    int tap = k >> 3, ic = k & 7;
                    float w = (ic < 6 && tap < 25 && oc < 30)
                            ? w1[(oc * 6 + ic) * 25 + tap] : 0.0f;
                    pk |= (uint32_t)f2bf(w) << (16 * e);
                }
                q[h * 2 + r] = pk;
            }
        }
        g_Bf1p[i] = make_uint4(q[0], q[1], q[2], q[3]);
    } else if (i < 13 * 2 * 32 + 18 * 4 * 4 * 32) {   // conv2: k = tap*32+ic
        int j = i - 13 * 2 * 32;
        int l = j & 31, jp = (j >> 5) & 3, nq = (j >> 7) & 3, s = j >> 9;
        uint32_t q[4] = {0, 0, 0, 0};
#pragma unroll
        for (int h = 0; h < 2; h++) {
            int nt = 2 * jp + h;
            int oc = nq * 64 + nt * 8 + (l >> 2);
            if (oc < 240) {
#pragma unroll
                for (int r = 0; r < 2; r++) {
                    uint32_t pk = 0;
#pragma unroll
                    for (int e = 0; e < 2; e++) {
                        int k = s * 16 + (l & 3) * 2 + r * 8 + e;
                        int tap = k >> 5, ic = k & 31;
                        float w = (ic < 30) ? w2[(oc * 30 + ic) * 9 + tap] : 0.0f;
                        pk |= (uint32_t)f2bf(w) << (16 * e);
                    }
                    q[h * 2 + r] = pk;
                }
            }
        }
        g_Bf2q[j] = make_uint4(q[0], q[1], q[2], q[3]);
    }
}

// ---------------------------------------------------------------------------
// Convert input NCHW f32 -> channel-last bf16 (coalesced both sides).
// ---------------------------------------------------------------------------
__global__ __launch_bounds__(256) void k_cvt(const float* __restrict__ in) {
    int p = blockIdx.x * 256 + threadIdx.x;
    if (p >= TT * HI * WI) return;
    int t  = p / (HI * WI);
    int px = p % (HI * WI);
    const float* b = in + (size_t)t * C1I * HI * WI + px;
    unsigned short r[8];
#pragma unroll
    for (int ic = 0; ic < 6; ic++) r[ic] = f2bf(b[(size_t)ic * HI * WI]);
    r[6] = 0; r[7] = 0;
    *(uint4*)(g_inb + (size_t)p * 8) = *(uint4*)r;
}

// ---------------------------------------------------------------------------
// Kernel 1: conv1 via mma.sync + fire(15) + maxpool 2x2 -> channel-last bf16.
// CTA (256 thr, 8 warps): 16x16 conv-px tile (M=256), N=32, K=208.
// ---------------------------------------------------------------------------
#define C1_IMG   0
#define C1_C     6400
#define C1_SMEM  (6400 + 32768)

__global__ __launch_bounds__(256) void k_conv1() {
    extern __shared__ __align__(16) unsigned char sm[];
    const uint32_t smb = cvta_smem(sm);
    float* sC = (float*)(sm + C1_C);           // [py16][px16][oc32]

    const int t   = blockIdx.z;
    const int X0  = blockIdx.x * 16;
    const int Y0  = blockIdx.y * 16;
    const int tid = threadIdx.x;
    const int wid = tid >> 5;
    const int l   = tid & 31;

    const unsigned short* inb = g_inb + (size_t)t * HI * WI * 8;
    for (int i = tid; i < 400; i += 256) {
        int ly = i / 20, lx = i % 20;
        int gy = Y0 - 2 + ly, gx = X0 - 2 + lx;
        bool ok = (unsigned)gy < (unsigned)HI && (unsigned)gx < (unsigned)WI;
        int cy = ok ? gy : 0, cx = ok ? gx : 0;
        const unsigned short* src = inb + ((size_t)cy * WI + cx) * 8;
        CP16Z(smb + C1_IMG + i * 16, src, ok ? 16 : 0);
    }
    CP_COMMIT();
    CP_WAIT(0);
    __syncthreads();

    float c[2][4][4];
#pragma unroll
    for (int i = 0; i < 2; i++)
#pragma unroll
        for (int nt = 0; nt < 4; nt++)
#pragma unroll
            for (int j = 0; j < 4; j++) c[i][nt][j] = 0.0f;

    const int pxl  = l & 15;
    const int tsel = l >> 4;

    for (int s = 0; s < 13; s++) {
        int tp = 2 * s + tsel; if (tp > 24) tp = 24;   // tap25: w=0, clamp addr
        int kh = tp / 5, kw = tp - 5 * kh;
#pragma unroll
        for (int i = 0; i < 2; i++) {
            int py = 2 * wid + i;
            uint32_t addr = smb + C1_IMG + ((py + kh) * 20 + pxl + kw) * 16;
            uint32_t a0, a1, a2, a3;
            asm volatile("ldmatrix.sync.aligned.m8n8.x4.shared.b16 {%0,%1,%2,%3}, [%4];"
                         : "=r"(a0), "=r"(a1), "=r"(a2), "=r"(a3) : "r"(addr));
            const uint4* bp = g_Bf1p + s * 64 + l;
#pragma unroll
            for (int jp = 0; jp < 2; jp++) {
                uint4 b = __ldg(bp + jp * 32);
                MMA16816(c[i][2*jp],   a0, a1, a2, a3, b.x, b.y);
                MMA16816(c[i][2*jp+1], a0, a1, a2, a3, b.z, b.w);
            }
        }
    }

#pragma unroll
    for (int i = 0; i < 2; i++) {
        int py = 2 * wid + i;
        int px0 = l >> 2, oc0 = 2 * (l & 3);
#pragma unroll
        for (int nt = 0; nt < 4; nt++) {
            *(float2*)(sC + (py * 16 + px0) * 32 + nt * 8 + oc0)
                = make_float2(c[i][nt][0], c[i][nt][1]);
            *(float2*)(sC + (py * 16 + px0 + 8) * 32 + nt * 8 + oc0)
                = make_float2(c[i][nt][2], c[i][nt][3]);
        }
    }
    __syncthreads();

    {
        int ocq = tid & 3;
        int ppx = (tid >> 2) & 7;
        int ppy = tid >> 5;
        uint32_t w[4];
#pragma unroll
        for (int u = 0; u < 4; u++) {
            uint32_t word = 0;
#pragma unroll
            for (int h = 0; h < 2; h++) {
                int oc = ocq * 8 + u * 2 + h;
                const float* p = sC + ((2 * ppy) * 16 + 2 * ppx) * 32 + oc;
                float m = fmaxf(fmaxf(p[0], p[32]), fmaxf(p[16 * 32], p[17 * 32]));
                if (m > 15.0f) word |= 0x3F80u << (16 * h);
            }
            w[u] = word;
        }
        int y = blockIdx.y * 8 + ppy + 1;
        int x = blockIdx.x * 8 + ppx + 1;
        *(uint4*)(g_spk1b + ((size_t)(t * HP + y) * WP + x) * 32 + ocq * 8)
            = make_uint4(w[0], w[1], w[2], w[3]);
    }
}

// ---------------------------------------------------------------------------
// Kernel 2: conv2 via mma.sync + fire(10), NO im2col, 2-step chunks.
// CTA (256 thr, 8 warps = 2mt x 4nq): M=64 (4py x 16px), N=256.
// A: raw halo [6][18] px x 80B (conflict-free ldmatrix, 5*px mod 8).
// B: 3-stage cp.async pipeline, 16KB chunks of 2 k-steps -> 9 barriers.
// 2 CTAs/SM.
// ---------------------------------------------------------------------------
#define HSTR   80
#define SB2    (6 * 18 * HSTR)         // 8640
#define SB_CHK 16384                   // 2 k-steps per chunk
#define SM2_BYTES (SB2 + 3 * SB_CHK)   // 57792

__global__ __launch_bounds__(256, 2) void k_conv2(float* __restrict__ spk,
                                                  float* __restrict__ pot) {
    extern __shared__ __align__(16) unsigned char sm[];
    const uint32_t smb = cvta_smem(sm);
    const int tid = threadIdx.x;
    const int wid = tid >> 5;
    const int l   = tid & 31;

    const int t   = blockIdx.z;
    const int OY0 = blockIdx.y * 4;
    const int OX0 = blockIdx.x * 16;

    // ---- Halo build: 108 px x 4 x 16B cp.async ----
    const unsigned short* spb = g_spk1b + (size_t)t * HP * WP * 32;
    for (int i = tid; i < 432; i += 256) {
        int u = i & 3, px = i >> 2;
        int ly = px / 18, lx = px - ly * 18;
        const unsigned short* src = spb + ((size_t)(OY0 + ly) * WP + OX0 + lx) * 32 + u * 8;
        CP16(smb + (ly * 18 + lx) * HSTR + u * 16, src);
    }

    // ---- B pipeline prologue: chunks of 2 steps (4 uint4 per thread) ----
    const uint4* bsrc0 = g_Bf2q + tid;        // chunk c at + c*1024
    const uint32_t bdst = smb + SB2 + tid * 16;

#pragma unroll
    for (int u = 0; u < 4; u++) CP16(bdst + u * 4096, bsrc0 + u * 256);
    CP_COMMIT();                              // g0 = halo + chunk 0
#pragma unroll
    for (int u = 0; u < 4; u++) CP16(bdst + SB_CHK + u * 4096, bsrc0 + 1024 + u * 256);
    CP_COMMIT();                              // g1 = chunk 1

    const int mt = wid & 1;                   // 2 mt x 4 nq
    const int nq = wid >> 1;

    const int pxl   = (l & 7) + ((l >> 3) & 1) * 8;   // matrix row = px
    const int khalf = (l >> 4) & 1;
    const uint32_t boff = SB2 + (nq * 128 + l) * 16;

    float c[2][8][4];
#pragma unroll
    for (int mi = 0; mi < 2; mi++)
#pragma unroll
        for (int nt = 0; nt < 8; nt++)
#pragma unroll
            for (int j = 0; j < 4; j++) c[mi][nt][j] = 0.0f;

    int stage = 0;
    for (int ck = 0; ck < 9; ck++) {
        if (ck < 8) { CP_WAIT(1); } else { CP_WAIT(0); }
        __syncthreads();
        if (ck + 2 < 9) {
            int st2 = stage + 2; if (st2 >= 3) st2 -= 3;
#pragma unroll
            for (int u = 0; u < 4; u++)
                CP16(bdst + st2 * SB_CHK + u * 4096,
                     bsrc0 + (size_t)(ck + 2) * 1024 + u * 256);
            CP_COMMIT();
        }

#pragma unroll
        for (int q = 0; q < 2; q++) {
            int s = 2 * ck + q;
            int tap = s >> 1, h = s & 1;
            int kh = (tap >= 6) ? 2 : (tap >= 3 ? 1 : 0);
            int kw = tap - 3 * kh;

            uint32_t a[2][4];
#pragma unroll
            for (int mi = 0; mi < 2; mi++) {
                int py = mt * 2 + mi;
                uint32_t addr = smb + ((py + kh) * 18 + pxl + kw) * HSTR
                              + h * 32 + khalf * 16;
                asm volatile("ldmatrix.sync.aligned.m8n8.x4.shared.b16 {%0,%1,%2,%3}, [%4];"
                             : "=r"(a[mi][0]), "=r"(a[mi][1]), "=r"(a[mi][2]), "=r"(a[mi][3])
                             : "r"(addr));
            }

            const unsigned char* bsm = sm + boff + stage * SB_CHK + q * 8192;
#pragma unroll
            for (int jp = 0; jp < 4; jp++) {
                uint4 b = *(const uint4*)(bsm + jp * 512);
#pragma unroll
                for (int mi = 0; mi < 2; mi++) {
                    MMA16816(c[mi][2*jp],   a[mi][0], a[mi][1], a[mi][2], a[mi][3], b.x, b.y);
                    MMA16816(c[mi][2*jp+1], a[mi][0], a[mi][1], a[mi][2], a[mi][3], b.z, b.w);
                }
            }
        }
        stage++; if (stage == 3) stage = 0;
    }

    // ---- Epilogue: fire(10), scatter stores ----
    const int g   = l >> 2;
    const int tig = l & 3;
    const size_t tb = (size_t)t * C2O * HO * WO;
    const size_t n2 = (size_t)TT * C2O * HO * WO;

#pragma unroll
    for (int mi = 0; mi < 2; mi++) {
        int yy = OY0 + mt * 2 + mi;
#pragma unroll
        for (int nt = 0; nt < 8; nt++) {
            int oc0 = nq * 64 + nt * 8 + 2 * tig;
            if (oc0 >= 240) continue;                  // N padding
#pragma unroll
            for (int j = 0; j < 4; j++) {
                int   oc = oc0 + (j & 1);
                int   xx = OX0 + g + ((j & 2) ? 8 : 0);
                float a  = c[mi][nt][j];
                size_t bi = tb + ((size_t)oc * HO + yy) * WO + xx;
                spk[bi]      = a > 10.0f ? 1.0f : 0.0f;
                spk[bi + n2] = a > 10.0f ? a : 0.0f;
            }
        }
    }
}

// ---------------------------------------------------------------------------
extern "C" void kernel_launch(void* const* d_in, const int* in_sizes, int n_in,
                              void* d_out, int out_size) {
    const float* in = (const float*)d_in[0];
    const float* w1 = (const float*)d_in[1];
    const float* w2 = (const float*)d_in[2];

    float* spk = (float*)d_out;
    const size_t n2 = (size_t)TT * C2O * HO * WO;
    float* pot = spk + n2;

    void* p1 = nullptr; cudaGetSymbolAddress(&p1, g_spk1b);
    cudaMemsetAsync(p1, 0, (size_t)TT * HP * WP * 32 * 2, 0);

    cudaFuncSetAttribute(k_conv1, cudaFuncAttributeMaxDynamicSharedMemorySize, C1_SMEM);
    cudaFuncSetAttribute(k_conv2, cudaFuncAttributeMaxDynamicSharedMemorySize, SM2_BYTES);

    const int nprep = 13 * 2 * 32 + 18 * 4 * 4 * 32;
    k_prep<<<(nprep + 255) / 256, 256>>>(w1, w2);
    k_cvt<<<(TT * HI * WI + 255) / 256, 256>>>(in);
    k_conv1<<<dim3(14, 14, TT), 256, C1_SMEM>>>();
    k_conv2<<<dim3(7, 28, TT), 256, SM2_BYTES>>>(spk, pot);
}

// round 17
// speedup vs baseline: 1.6091x; 1.0488x over previous
#include <cuda_runtime.h>
#include <cuda_bf16.h>
#include <cstdint>

#define TT  15
#define C1I 6
#define HI  224
#define WI  224
#define C1O 30
#define HP  114
#define WP  114
#define C2O 240
#define HO  112
#define WO  112

// Input, channel-last bf16: [t][y(224)][x(224)][8]
__device__ __align__(16) unsigned short g_inb[(size_t)TT * HI * WI * 8];
// Layer-1 pooled spikes, channel-last bf16, padded: [t][y(114)][x(114)][32]
__device__ __align__(16) unsigned short g_spk1b[(size_t)TT * HP * WP * 32];
// Conv1 B-fragments, nt-paired: [s(13)][jp(2)][lane(32)] uint4
__device__ __align__(16) uint4 g_Bf1p[13 * 2 * 32];
// Conv2 B-fragments, per-warp-private: [s(18)][nv(8)][jp(2)][lane(32)] uint4
// oc = nv*32 + jp*16 + h*8 + (l>>2); h selects (x,y)/(z,w) halves.
__device__ __align__(16) uint4 g_Bf2q[18 * 8 * 2 * 32];

__device__ __forceinline__ uint32_t cvta_smem(const void* p) {
    uint32_t a;
    asm("{ .reg .u64 t; cvta.to.shared.u64 t, %1; cvt.u32.u64 %0, t; }"
        : "=r"(a) : "l"(p));
    return a;
}
__device__ __forceinline__ unsigned short f2bf(float f) {
    __nv_bfloat16 b = __float2bfloat16(f);
    return *(unsigned short*)&b;
}

#define CP16(dst, src) \
    asm volatile("cp.async.cg.shared.global [%0], [%1], 16;" \
                 :: "r"(dst), "l"(src) : "memory")
#define CP16Z(dst, src, sz) \
    asm volatile("cp.async.cg.shared.global [%0], [%1], 16, %2;" \
                 :: "r"(dst), "l"(src), "r"(sz) : "memory")
#define CP_COMMIT() asm volatile("cp.async.commit_group;" ::: "memory")
#define CP_WAIT(n)  asm volatile("cp.async.wait_group %0;" :: "n"(n) : "memory")

#define MMA16816(c, a0, a1, a2, a3, b0, b1) \
    asm volatile( \
        "mma.sync.aligned.m16n8k16.row.col.f32.bf16.bf16.f32 " \
        "{%0,%1,%2,%3}, {%4,%5,%6,%7}, {%8,%9}, {%0,%1,%2,%3};" \
        : "+f"((c)[0]), "+f"((c)[1]), "+f"((c)[2]), "+f"((c)[3]) \
        : "r"(a0), "r"(a1), "r"(a2), "r"(a3), "r"(b0), "r"(b1))

// ---------------------------------------------------------------------------
// Prep: B-fragments (m16n8k16 .row.col: lane l holds n=l>>2, k=(l&3)*2+r*8+e).
// ---------------------------------------------------------------------------
__global__ __launch_bounds__(256) void k_prep(const float* __restrict__ w1,
                                              const float* __restrict__ w2) {
    int i = blockIdx.x * 256 + threadIdx.x;
    if (i < 13 * 2 * 32) {                       // conv1: k = tap*8+ic
        int l = i & 31, jp = (i >> 5) & 1, s = i >> 6;
        uint32_t q[4];
#pragma unroll
        for (int h = 0; h < 2; h++) {
            int nt = 2 * jp + h;
            int oc = nt * 8 + (l >> 2);
#pragma unroll
            for (int r = 0; r < 2; r++) {
                uint32_t pk = 0;
#pragma unroll
                for (int e = 0; e < 2; e++) {
                    int k = s * 16 + (l & 3) * 2 + r * 8 + e;
                    int tap = k >> 3, ic = k & 7;
                    float w = (ic < 6 && tap < 25 && oc < 30)
                            ? w1[(oc * 6 + ic) * 25 + tap] : 0.0f;
                    pk |= (uint32_t)f2bf(w) << (16 * e);
                }
                q[h * 2 + r] = pk;
            }
        }
        g_Bf1p[i] = make_uint4(q[0], q[1], q[2], q[3]);
    } else if (i < 13 * 2 * 32 + 18 * 8 * 2 * 32) {   // conv2: k = tap*32+ic
        int j = i - 13 * 2 * 32;
        int l = j & 31, jp = (j >> 5) & 1, nv = (j >> 6) & 7, s = j >> 9;
        uint32_t q[4] = {0, 0, 0, 0};
#pragma unroll
        for (int h = 0; h < 2; h++) {
            int oc = nv * 32 + jp * 16 + h * 8 + (l >> 2);
            if (oc < 240) {
#pragma unroll
                for (int r = 0; r < 2; r++) {
                    uint32_t pk = 0;
#pragma unroll
                    for (int e = 0; e < 2; e++) {
                        int k = s * 16 + (l & 3) * 2 + r * 8 + e;
                        int tap = k >> 5, ic = k & 31;
                        float w = (ic < 30) ? w2[(oc * 30 + ic) * 9 + tap] : 0.0f;
                        pk |= (uint32_t)f2bf(w) << (16 * e);
                    }
                    q[h * 2 + r] = pk;
                }
            }
        }
        g_Bf2q[j] = make_uint4(q[0], q[1], q[2], q[3]);
    }
}

// ---------------------------------------------------------------------------
// Convert input NCHW f32 -> channel-last bf16 (coalesced both sides).
// ---------------------------------------------------------------------------
__global__ __launch_bounds__(256) void k_cvt(const float* __restrict__ in) {
    int p = blockIdx.x * 256 + threadIdx.x;
    if (p >= TT * HI * WI) return;
    int t  = p / (HI * WI);
    int px = p % (HI * WI);
    const float* b = in + (size_t)t * C1I * HI * WI + px;
    unsigned short r[8];
#pragma unroll
    for (int ic = 0; ic < 6; ic++) r[ic] = f2bf(b[(size_t)ic * HI * WI]);
    r[6] = 0; r[7] = 0;
    *(uint4*)(g_inb + (size_t)p * 8) = *(uint4*)r;
}

// ---------------------------------------------------------------------------
// Kernel 1: conv1 via mma.sync + fire(15) + maxpool 2x2 -> channel-last bf16.
// CTA (256 thr, 8 warps): 16x16 conv-px tile (M=256), N=32, K=208.
// ---------------------------------------------------------------------------
#define C1_IMG   0
#define C1_C     6400
#define C1_SMEM  (6400 + 32768)

__global__ __launch_bounds__(256) void k_conv1() {
    extern __shared__ __align__(16) unsigned char sm[];
    const uint32_t smb = cvta_smem(sm);
    float* sC = (float*)(sm + C1_C);           // [py16][px16][oc32]

    const int t   = blockIdx.z;
    const int X0  = blockIdx.x * 16;
    const int Y0  = blockIdx.y * 16;
    const int tid = threadIdx.x;
    const int wid = tid >> 5;
    const int l   = tid & 31;

    const unsigned short* inb = g_inb + (size_t)t * HI * WI * 8;
    for (int i = tid; i < 400; i += 256) {
        int ly = i / 20, lx = i % 20;
        int gy = Y0 - 2 + ly, gx = X0 - 2 + lx;
        bool ok = (unsigned)gy < (unsigned)HI && (unsigned)gx < (unsigned)WI;
        int cy = ok ? gy : 0, cx = ok ? gx : 0;
        const unsigned short* src = inb + ((size_t)cy * WI + cx) * 8;
        CP16Z(smb + C1_IMG + i * 16, src, ok ? 16 : 0);
    }
    CP_COMMIT();
    CP_WAIT(0);
    __syncthreads();

    float c[2][4][4];
#pragma unroll
    for (int i = 0; i < 2; i++)
#pragma unroll
        for (int nt = 0; nt < 4; nt++)
#pragma unroll
            for (int j = 0; j < 4; j++) c[i][nt][j] = 0.0f;

    const int pxl  = l & 15;
    const int tsel = l >> 4;

    for (int s = 0; s < 13; s++) {
        int tp = 2 * s + tsel; if (tp > 24) tp = 24;   // tap25: w=0, clamp addr
        int kh = tp / 5, kw = tp - 5 * kh;
#pragma unroll
        for (int i = 0; i < 2; i++) {
            int py = 2 * wid + i;
            uint32_t addr = smb + C1_IMG + ((py + kh) * 20 + pxl + kw) * 16;
            uint32_t a0, a1, a2, a3;
            asm volatile("ldmatrix.sync.aligned.m8n8.x4.shared.b16 {%0,%1,%2,%3}, [%4];"
                         : "=r"(a0), "=r"(a1), "=r"(a2), "=r"(a3) : "r"(addr));
            const uint4* bp = g_Bf1p + s * 64 + l;
#pragma unroll
            for (int jp = 0; jp < 2; jp++) {
                uint4 b = __ldg(bp + jp * 32);
                MMA16816(c[i][2*jp],   a0, a1, a2, a3, b.x, b.y);
                MMA16816(c[i][2*jp+1], a0, a1, a2, a3, b.z, b.w);
            }
        }
    }

#pragma unroll
    for (int i = 0; i < 2; i++) {
        int py = 2 * wid + i;
        int px0 = l >> 2, oc0 = 2 * (l & 3);
#pragma unroll
        for (int nt = 0; nt < 4; nt++) {
            *(float2*)(sC + (py * 16 + px0) * 32 + nt * 8 + oc0)
                = make_float2(c[i][nt][0], c[i][nt][1]);
            *(float2*)(sC + (py * 16 + px0 + 8) * 32 + nt * 8 + oc0)
                = make_float2(c[i][nt][2], c[i][nt][3]);
        }
    }
    __syncthreads();

    {
        int ocq = tid & 3;
        int ppx = (tid >> 2) & 7;
        int ppy = tid >> 5;
        uint32_t w[4];
#pragma unroll
        for (int u = 0; u < 4; u++) {
            uint32_t word = 0;
#pragma unroll
            for (int h = 0; h < 2; h++) {
                int oc = ocq * 8 + u * 2 + h;
                const float* p = sC + ((2 * ppy) * 16 + 2 * ppx) * 32 + oc;
                float m = fmaxf(fmaxf(p[0], p[32]), fmaxf(p[16 * 32], p[17 * 32]));
                if (m > 15.0f) word |= 0x3F80u << (16 * h);
            }
            w[u] = word;
        }
        int y = blockIdx.y * 8 + ppy + 1;
        int x = blockIdx.x * 8 + ppx + 1;
        *(uint4*)(g_spk1b + ((size_t)(t * HP + y) * WP + x) * 32 + ocq * 8)
            = make_uint4(w[0], w[1], w[2], w[3]);
    }
}

// ---------------------------------------------------------------------------
// Kernel 2: conv2 via mma.sync + fire(10) — warp-autonomous, NO mainloop
// barriers. CTA (256 thr, 8 warps = 8 N-slices): M=64 (4py x 16px), N=256.
// Warp tile M64 x N32: 4 ldmatrix + 2 private B-LDS.128 -> 16 mma per step.
// B is per-thread-private: each thread cp.asyncs its own 2 uint4 per step
// (4-stage ring, depth-3 prefetch, cp.async.wait_group only).
// A: raw halo [6][18] px x 80B (conflict-free, 5*px mod 8). 2 CTAs/SM.
// ---------------------------------------------------------------------------
#define HSTR   80
#define SB2    (6 * 18 * HSTR)         // 8640
#define SB_STG 8192                    // one k-step of B
#define SM2_BYTES (SB2 + 4 * SB_STG)   // 41408

__global__ __launch_bounds__(256, 2) void k_conv2(float* __restrict__ spk,
                                                  float* __restrict__ pot) {
    extern __shared__ __align__(16) unsigned char sm[];
    const uint32_t smb = cvta_smem(sm);
    const int tid = threadIdx.x;
    const int nv  = tid >> 5;                 // warp = N-slice
    const int l   = tid & 31;

    const int t   = blockIdx.z;
    const int OY0 = blockIdx.y * 4;
    const int OX0 = blockIdx.x * 16;

    // ---- Halo build: 108 px x 4 x 16B cp.async ----
    const unsigned short* spb = g_spk1b + (size_t)t * HP * WP * 32;
    for (int i = tid; i < 432; i += 256) {
        int u = i & 3, px = i >> 2;
        int ly = px / 18, lx = px - ly * 18;
        const unsigned short* src = spb + ((size_t)(OY0 + ly) * WP + OX0 + lx) * 32 + u * 8;
        CP16(smb + (ly * 18 + lx) * HSTR + u * 16, src);
    }

    // ---- Per-thread B pipeline: thread owns [s][nv][jp 0..1][l] ----
    const uint4* bsrc = g_Bf2q + (nv * 2) * 32 + l;      // + s*512, jp at +32
    const uint32_t bdst = smb + SB2 + ((nv * 2) * 32 + l) * 16;  // jp at +512

    CP16(bdst, bsrc);               CP16(bdst + 512, bsrc + 32);        // s0
    CP_COMMIT();                                   // g0 = halo + B0
    CP16(bdst + SB_STG, bsrc + 512); CP16(bdst + SB_STG + 512, bsrc + 544);
    CP_COMMIT();                                   // g1 = B1
    CP16(bdst + 2*SB_STG, bsrc + 1024); CP16(bdst + 2*SB_STG + 512, bsrc + 1056);
    CP_COMMIT();                                   // g2 = B2

    CP_WAIT(2);                 // halo + B0 done (own contributions)
    __syncthreads();            // publish halo; last barrier in the kernel

    const int pxl   = (l & 7) + ((l >> 3) & 1) * 8;   // matrix row = px
    const int khalf = (l >> 4) & 1;

    float c[4][4][4];           // [mi][nt'][j], nt' = 2*jp + h
#pragma unroll
    for (int mi = 0; mi < 4; mi++)
#pragma unroll
        for (int nt = 0; nt < 4; nt++)
#pragma unroll
            for (int j = 0; j < 4; j++) c[mi][nt][j] = 0.0f;

    for (int s = 0; s < 18; s++) {
        if (s > 0) {
            if (s < 16)      { CP_WAIT(2); }
            else if (s == 16){ CP_WAIT(1); }
            else             { CP_WAIT(0); }
        }
        if (s + 3 < 18) {
            int st = (s + 3) & 3;
            CP16(bdst + st * SB_STG,       bsrc + (size_t)(s + 3) * 512);
            CP16(bdst + st * SB_STG + 512, bsrc + (size_t)(s + 3) * 512 + 32);
            CP_COMMIT();
        }

        int tap = s >> 1, h2 = s & 1;
        int kh = (tap >= 6) ? 2 : (tap >= 3 ? 1 : 0);
        int kw = tap - 3 * kh;

        uint32_t a[4][4];
#pragma unroll
        for (int mi = 0; mi < 4; mi++) {
            uint32_t addr = smb + ((mi + kh) * 18 + pxl + kw) * HSTR
                          + h2 * 32 + khalf * 16;
            asm volatile("ldmatrix.sync.aligned.m8n8.x4.shared.b16 {%0,%1,%2,%3}, [%4];"
                         : "=r"(a[mi][0]), "=r"(a[mi][1]), "=r"(a[mi][2]), "=r"(a[mi][3])
                         : "r"(addr));
        }

        const unsigned char* bsm = sm + SB2 + (s & 3) * SB_STG + ((nv * 2) * 32 + l) * 16;
#pragma unroll
        for (int jp = 0; jp < 2; jp++) {
            uint4 b = *(const uint4*)(bsm + jp * 512);
#pragma unroll
            for (int mi = 0; mi < 4; mi++) {
                MMA16816(c[mi][2*jp],   a[mi][0], a[mi][1], a[mi][2], a[mi][3], b.x, b.y);
                MMA16816(c[mi][2*jp+1], a[mi][0], a[mi][1], a[mi][2], a[mi][3], b.z, b.w);
            }
        }
    }

    // ---- Epilogue: fire(10), scatter stores ----
    const size_t tb = (size_t)t * C2O * HO * WO;
    const size_t n2 = (size_t)TT * C2O * HO * WO;

#pragma unroll
    for (int mi = 0; mi < 4; mi++) {
#pragma unroll
        for (int nt = 0; nt < 4; nt++) {
            int oc0 = nv * 32 + nt * 8 + 2 * (l & 3);
            if (oc0 >= 240) continue;                  // N padding (nv=7 tail)
#pragma unroll
            for (int j = 0; j < 4; j++) {
                int   oc = oc0 + (j & 1);
                int   m  = mi * 16 + (l >> 2) + ((j & 2) ? 8 : 0);
                int   yy = OY0 + (m >> 4);
                int   xx = OX0 + (m & 15);
                float a  = c[mi][nt][j];
                size_t bi = tb + ((size_t)oc * HO + yy) * WO + xx;
                spk[bi]      = a > 10.0f ? 1.0f : 0.0f;
                spk[bi + n2] = a > 10.0f ? a : 0.0f;
            }
        }
    }
}

// ---------------------------------------------------------------------------
extern "C" void kernel_launch(void* const* d_in, const int* in_sizes, int n_in,
                              void* d_out, int out_size) {
    const float* in = (const float*)d_in[0];
    const float* w1 = (const float*)d_in[1];
    const float* w2 = (const float*)d_in[2];

    float* spk = (float*)d_out;
    const size_t n2 = (size_t)TT * C2O * HO * WO;
    float* pot = spk + n2;

    void* p1 = nullptr; cudaGetSymbolAddress(&p1, g_spk1b);
    cudaMemsetAsync(p1, 0, (size_t)TT * HP * WP * 32 * 2, 0);

    cudaFuncSetAttribute(k_conv1, cudaFuncAttributeMaxDynamicSharedMemorySize, C1_SMEM);
    cudaFuncSetAttribute(k_conv2, cudaFuncAttributeMaxDynamicSharedMemorySize, SM2_BYTES);

    const int nprep = 13 * 2 * 32 + 18 * 8 * 2 * 32;
    k_prep<<<(nprep + 255) / 256, 256>>>(w1, w2);
    k_cvt<<<(TT * HI * WI + 255) / 256, 256>>>(in);
    k_conv1<<<dim3(14, 14, TT), 256, C1_SMEM>>>();
    k_conv2<<<dim3(7, 28, TT), 256, SM2_BYTES>>>(spk, pot);
}